// round 2
// baseline (speedup 1.0000x reference)
#include <cuda_runtime.h>

#define NNODES 50000
#define DDIM 128
#define NH 8
#define HDIM 16
#define FDIM 512
#define E0 800000
#define ETOT 850000
#define EPS_BN 1e-5f

// ---------------- scratch (device globals; no allocation allowed) ----------
__device__ __align__(16) float g_q[NNODES * DDIM];
__device__ __align__(16) float g_k[NNODES * DDIM];
__device__ __align__(16) float g_v[NNODES * DDIM];
__device__ __align__(16) float g_ex[(size_t)ETOT * NH];
__device__ __align__(16) float g_den[NNODES * NH];
__device__ __align__(16) float g_agg[NNODES * DDIM];
__device__ __align__(16) float g_x1[NNODES * DDIM];
__device__ __align__(16) float g_tmp[NNODES * DDIM];
__device__ __align__(16) float g_ff1[(size_t)NNODES * FDIM];
__device__ __align__(16) float g_stats[512];
__device__ int g_src[ETOT];
__device__ int g_dst[ETOT];
__device__ int g_is64;

// ---------------- edge index dtype detection + decode ----------------------
// If edge_index survived as int64 (little-endian, values < 50000), every odd
// 32-bit word of the buffer is zero. If it was narrowed to int32, odd words
// are random node ids. Inspect 128 odd words to decide.
__global__ void detect_kernel(const unsigned int* __restrict__ w) {
    if (threadIdx.x == 0 && blockIdx.x == 0) {
        int nz = 0;
        for (int i = 1; i < 256; i += 2) nz += (w[i] != 0u);
        g_is64 = (nz == 0) ? 1 : 0;
    }
}

__global__ void decode_kernel(const unsigned int* __restrict__ w) {
    int e = blockIdx.x * blockDim.x + threadIdx.x;
    if (e >= ETOT) return;
    if (e < E0) {
        int s, d;
        if (g_is64) {
            s = (int)w[2 * (size_t)e];
            d = (int)w[2 * ((size_t)E0 + e)];
        } else {
            s = (int)w[e];
            d = (int)w[E0 + e];
        }
        g_src[e] = s;
        g_dst[e] = d;
    } else {
        g_src[e] = e - E0;
        g_dst[e] = e - E0;
    }
}

// ---------------- zero scratch ---------------------------------------------
__global__ void zero_kernel() {
    int i = blockIdx.x * blockDim.x + threadIdx.x;
    int stride = gridDim.x * blockDim.x;
    for (int t = i; t < NNODES * NH; t += stride) g_den[t] = 0.f;
    for (int t = i; t < NNODES * DDIM; t += stride) g_agg[t] = 0.f;
    if (i < 512) g_stats[i] = 0.f;
}

// ---------------- generic tiled fp32 GEMM: C = act((A@B^T + bias)*alpha + res)
#define BM 64
#define BN 64
#define BK 16

__global__ __launch_bounds__(256) void gemm_kernel(
    const float* __restrict__ A, const float* __restrict__ B,
    const float* __restrict__ bias, const float* __restrict__ res,
    float* __restrict__ C, int M, int Nn, int K, float alpha, int act)
{
    __shared__ __align__(16) float As[BK][BM];
    __shared__ __align__(16) float Bs[BK][BN];
    int tid = threadIdx.x;
    int bm = blockIdx.y * BM;
    int bn = blockIdx.x * BN;
    int tx = tid & 15, ty = tid >> 4;
    int row = ty * 4, col = tx * 4;
    int lr = tid >> 2;           // 0..63
    int lc = (tid & 3) * 4;      // 0,4,8,12

    float acc[4][4] = {};
    int arow = bm + lr;
    const float* Aptr = A + (size_t)arow * K + lc;
    const float* Bptr = B + (size_t)(bn + lr) * K + lc;

    for (int k0 = 0; k0 < K; k0 += BK) {
        float4 a4 = make_float4(0.f, 0.f, 0.f, 0.f);
        if (arow < M) a4 = *(const float4*)(Aptr + k0);
        float4 b4 = *(const float4*)(Bptr + k0);
        As[lc + 0][lr] = a4.x; As[lc + 1][lr] = a4.y;
        As[lc + 2][lr] = a4.z; As[lc + 3][lr] = a4.w;
        Bs[lc + 0][lr] = b4.x; Bs[lc + 1][lr] = b4.y;
        Bs[lc + 2][lr] = b4.z; Bs[lc + 3][lr] = b4.w;
        __syncthreads();
#pragma unroll
        for (int kk = 0; kk < BK; kk++) {
            float4 av = *(const float4*)&As[kk][row];
            float4 bv = *(const float4*)&Bs[kk][col];
            float a_[4] = {av.x, av.y, av.z, av.w};
            float b_[4] = {bv.x, bv.y, bv.z, bv.w};
#pragma unroll
            for (int i = 0; i < 4; i++)
#pragma unroll
                for (int j = 0; j < 4; j++)
                    acc[i][j] += a_[i] * b_[j];
        }
        __syncthreads();
    }

    int cbase = bn + col;
    float bb[4] = {0.f, 0.f, 0.f, 0.f};
    if (bias) {
        bb[0] = bias[cbase + 0]; bb[1] = bias[cbase + 1];
        bb[2] = bias[cbase + 2]; bb[3] = bias[cbase + 3];
    }
#pragma unroll
    for (int i = 0; i < 4; i++) {
        int r = bm + row + i;
        if (r >= M) continue;
        float4 rv = make_float4(0.f, 0.f, 0.f, 0.f);
        if (res) rv = *(const float4*)(res + (size_t)r * Nn + cbase);
        float4 o;
        o.x = (acc[i][0] + bb[0]) * alpha + rv.x;
        o.y = (acc[i][1] + bb[1]) * alpha + rv.y;
        o.z = (acc[i][2] + bb[2]) * alpha + rv.z;
        o.w = (acc[i][3] + bb[3]) * alpha + rv.w;
        if (act) {
            o.x = o.x > 0.f ? o.x : 0.01f * o.x;
            o.y = o.y > 0.f ? o.y : 0.01f * o.y;
            o.z = o.z > 0.f ? o.z : 0.01f * o.z;
            o.w = o.w > 0.f ? o.w : 0.01f * o.w;
        }
        *(float4*)(C + (size_t)r * Nn + cbase) = o;
    }
}

// ---------------- edge scores + exp + denominator --------------------------
// softmax max elided: q,k ~ N(0, small), |score| << 80, exp() safe in fp32.
__global__ void edge_scores_kernel() {
    int gwarp = (blockIdx.x * blockDim.x + threadIdx.x) >> 5;
    if (gwarp >= ETOT) return;
    int lane = threadIdx.x & 31;
    int s = g_src[gwarp];
    int d = g_dst[gwarp];
    float4 q4 = *(const float4*)(g_q + (size_t)d * DDIM + lane * 4);
    float4 k4 = *(const float4*)(g_k + (size_t)s * DDIM + lane * 4);
    float p = q4.x * k4.x + q4.y * k4.y + q4.z * k4.z + q4.w * k4.w;
    p += __shfl_xor_sync(0xffffffffu, p, 1);
    p += __shfl_xor_sync(0xffffffffu, p, 2);
    if ((lane & 3) == 0) {
        int h = lane >> 2;
        float e = __expf(p);
        g_ex[(size_t)gwarp * NH + h] = e;
        atomicAdd(&g_den[d * NH + h], e);
    }
}

// ---------------- weighted scatter-add aggregation --------------------------
__global__ void edge_agg_kernel() {
    int gwarp = (blockIdx.x * blockDim.x + threadIdx.x) >> 5;
    if (gwarp >= ETOT) return;
    int lane = threadIdx.x & 31;
    int s = g_src[gwarp];
    int d = g_dst[gwarp];
    int h = lane >> 2;
    float a = g_ex[(size_t)gwarp * NH + h] / (g_den[d * NH + h] + 1e-16f);
    float4 v4 = *(const float4*)(g_v + (size_t)s * DDIM + lane * 4);
    float* dst = g_agg + (size_t)d * DDIM + lane * 4;
    atomicAdd(dst + 0, a * v4.x);
    atomicAdd(dst + 1, a * v4.y);
    atomicAdd(dst + 2, a * v4.z);
    atomicAdd(dst + 3, a * v4.w);
}

// ---------------- BatchNorm stats + apply ----------------------------------
__global__ void bn_stats_kernel(const float* __restrict__ X, int off) {
    int j = threadIdx.x;  // 128
    float s = 0.f, ss = 0.f;
    for (int r = blockIdx.x; r < NNODES; r += gridDim.x) {
        float x = X[(size_t)r * DDIM + j];
        s += x;
        ss += x * x;
    }
    atomicAdd(&g_stats[off + j], s);
    atomicAdd(&g_stats[off + DDIM + j], ss);
}

__global__ void bn_apply_kernel(const float* __restrict__ X, int off,
                                const float* __restrict__ gamma,
                                const float* __restrict__ beta,
                                float* __restrict__ Y) {
    int i = blockIdx.x * blockDim.x + threadIdx.x;
    if (i >= NNODES * DDIM) return;
    int j = i & (DDIM - 1);
    const float invn = 1.0f / NNODES;
    float mean = g_stats[off + j] * invn;
    float var = g_stats[off + DDIM + j] * invn - mean * mean;
    float x = X[i];
    Y[i] = (x - mean) * rsqrtf(var + EPS_BN) * gamma[j] + beta[j];
}

// ---------------- launch ----------------------------------------------------
extern "C" void kernel_launch(void* const* d_in, const int* in_sizes, int n_in,
                              void* d_out, int out_size) {
    const float* src    = (const float*)d_in[0];
    const unsigned int* ei = (const unsigned int*)d_in[1];
    const float* q_w    = (const float*)d_in[2];
    const float* q_b    = (const float*)d_in[3];
    const float* k_w    = (const float*)d_in[4];
    const float* v_w    = (const float*)d_in[5];
    const float* out_w  = (const float*)d_in[6];
    const float* out_b  = (const float*)d_in[7];
    const float* g1     = (const float*)d_in[8];
    const float* b1     = (const float*)d_in[9];
    const float* lin1_w = (const float*)d_in[10];
    const float* lin1_b = (const float*)d_in[11];
    const float* lin2_w = (const float*)d_in[12];
    const float* lin2_b = (const float*)d_in[13];
    const float* g2     = (const float*)d_in[14];
    const float* b2     = (const float*)d_in[15];
    float* out = (float*)d_out;

    float *pq, *pagg, *px1, *ptmp, *pff1;
    cudaGetSymbolAddress((void**)&pq,   g_q);
    float *pk, *pv;
    cudaGetSymbolAddress((void**)&pk,   g_k);
    cudaGetSymbolAddress((void**)&pv,   g_v);
    cudaGetSymbolAddress((void**)&pagg, g_agg);
    cudaGetSymbolAddress((void**)&px1,  g_x1);
    cudaGetSymbolAddress((void**)&ptmp, g_tmp);
    cudaGetSymbolAddress((void**)&pff1, g_ff1);

    const int MB = (NNODES + BM - 1) / BM;  // 782
    const float scaling = 0.25f;            // HD^-0.5

    detect_kernel<<<1, 32>>>(ei);
    decode_kernel<<<(ETOT + 255) / 256, 256>>>(ei);
    zero_kernel<<<512, 256>>>();

    // q, k, v projections
    gemm_kernel<<<dim3(DDIM / BN, MB), 256>>>(src, q_w, q_b, nullptr, pq,
                                              NNODES, DDIM, DDIM, scaling, 0);
    gemm_kernel<<<dim3(DDIM / BN, MB), 256>>>(src, k_w, nullptr, nullptr, pk,
                                              NNODES, DDIM, DDIM, 1.0f, 0);
    gemm_kernel<<<dim3(DDIM / BN, MB), 256>>>(src, v_w, nullptr, nullptr, pv,
                                              NNODES, DDIM, DDIM, 1.0f, 0);

    // edge attention
    int eblocks = (ETOT * 32 + 255) / 256;
    edge_scores_kernel<<<eblocks, 256>>>();
    edge_agg_kernel<<<eblocks, 256>>>();

    // out projection + residual
    gemm_kernel<<<dim3(DDIM / BN, MB), 256>>>(pagg, out_w, out_b, src, ptmp,
                                              NNODES, DDIM, DDIM, 1.0f, 0);

    // BN1
    bn_stats_kernel<<<512, 128>>>(ptmp, 0);
    bn_apply_kernel<<<(NNODES * DDIM + 255) / 256, 256>>>(ptmp, 0, g1, b1, px1);

    // FFN
    gemm_kernel<<<dim3(FDIM / BN, MB), 256>>>(px1, lin1_w, lin1_b, nullptr, pff1,
                                              NNODES, FDIM, DDIM, 1.0f, 1);
    gemm_kernel<<<dim3(DDIM / BN, MB), 256>>>(pff1, lin2_w, lin2_b, px1, ptmp,
                                              NNODES, DDIM, FDIM, 1.0f, 0);

    // BN2 -> output
    bn_stats_kernel<<<512, 128>>>(ptmp, 256);
    bn_apply_kernel<<<(NNODES * DDIM + 255) / 256, 256>>>(ptmp, 256, g2, b2, out);
}

// round 3
// speedup vs baseline: 1.2913x; 1.2913x over previous
#include <cuda_runtime.h>

#define NNODES 50000
#define DDIM 128
#define NH 8
#define HDIM 16
#define FDIM 512
#define E0 800000
#define ETOT 850000
#define EPS_BN 1e-5f

// ---------------- scratch (device globals; no allocation allowed) ----------
__device__ __align__(16) float g_q[NNODES * DDIM];
__device__ __align__(16) float g_k[NNODES * DDIM];
__device__ __align__(16) float g_v[NNODES * DDIM];
__device__ __align__(16) float g_den[NNODES * NH];
__device__ __align__(16) float g_agg[NNODES * DDIM];
__device__ __align__(16) float g_x1[NNODES * DDIM];
__device__ __align__(16) float g_tmp[NNODES * DDIM];
__device__ __align__(16) float g_ff1[(size_t)NNODES * FDIM];
__device__ __align__(16) float g_stats[512];
__device__ int g_src[ETOT];
__device__ int g_dst[ETOT];
__device__ int g_is64;

// ---------------- edge index dtype detection + decode ----------------------
__global__ void detect_kernel(const unsigned int* __restrict__ w) {
    if (threadIdx.x == 0 && blockIdx.x == 0) {
        int nz = 0;
        for (int i = 1; i < 256; i += 2) nz += (w[i] != 0u);
        g_is64 = (nz == 0) ? 1 : 0;
    }
}

__global__ void decode_kernel(const unsigned int* __restrict__ w) {
    int e = blockIdx.x * blockDim.x + threadIdx.x;
    if (e >= ETOT) return;
    if (e < E0) {
        int s, d;
        if (g_is64) {
            s = (int)w[2 * (size_t)e];
            d = (int)w[2 * ((size_t)E0 + e)];
        } else {
            s = (int)w[e];
            d = (int)w[E0 + e];
        }
        g_src[e] = s;
        g_dst[e] = d;
    } else {
        g_src[e] = e - E0;
        g_dst[e] = e - E0;
    }
}

// ---------------- zero scratch ---------------------------------------------
__global__ void zero_kernel() {
    int i = blockIdx.x * blockDim.x + threadIdx.x;
    int stride = gridDim.x * blockDim.x;
    for (int t = i; t < NNODES * NH; t += stride) g_den[t] = 0.f;
    for (int t = i; t < NNODES * DDIM; t += stride) g_agg[t] = 0.f;
    if (i < 512) g_stats[i] = 0.f;
}

// ---------------- tiled fp32 GEMM, 8x8 microtile, double-buffered ----------
// C = act((A@B^T + bias)*alpha + res). A[M,K], B[N,K] row-major.
// Nn % 128 == 0, K % 16 == 0.
#define GM 128
#define GN 128
#define GKK 16

__global__ __launch_bounds__(256, 2) void gemm_kernel(
    const float* __restrict__ A, const float* __restrict__ B,
    const float* __restrict__ bias, const float* __restrict__ res,
    float* __restrict__ C, int M, int Nn, int K, float alpha, int act)
{
    __shared__ __align__(16) float As[2][GKK][GM];
    __shared__ __align__(16) float Bs[2][GKK][GN];
    int tid = threadIdx.x;
    int bm = blockIdx.y * GM;
    int bn = blockIdx.x * GN;
    int tx = tid & 15, ty = tid >> 4;
    int row = ty * 8, col = tx * 8;

    // loaders: 2 float4 per thread per tile (128x16 floats / 256 threads)
    int ar0 = tid >> 2;              // 0..63
    int ar1 = ar0 + 64;              // 64..127
    int ac = (tid & 3) * 4;          // 0,4,8,12

    const float* Ap0 = A + (size_t)(bm + ar0) * K + ac;
    const float* Ap1 = A + (size_t)(bm + ar1) * K + ac;
    const float* Bp0 = B + (size_t)(bn + ar0) * K + ac;
    const float* Bp1 = B + (size_t)(bn + ar1) * K + ac;
    bool av0ok = (bm + ar0) < M;
    bool av1ok = (bm + ar1) < M;

    float acc[8][8] = {};

    // prologue: load tile 0 into buffer 0
    float4 a0 = av0ok ? *(const float4*)Ap0 : make_float4(0.f, 0.f, 0.f, 0.f);
    float4 a1 = av1ok ? *(const float4*)Ap1 : make_float4(0.f, 0.f, 0.f, 0.f);
    float4 b0 = *(const float4*)Bp0;
    float4 b1 = *(const float4*)Bp1;
    As[0][ac + 0][ar0] = a0.x; As[0][ac + 1][ar0] = a0.y;
    As[0][ac + 2][ar0] = a0.z; As[0][ac + 3][ar0] = a0.w;
    As[0][ac + 0][ar1] = a1.x; As[0][ac + 1][ar1] = a1.y;
    As[0][ac + 2][ar1] = a1.z; As[0][ac + 3][ar1] = a1.w;
    Bs[0][ac + 0][ar0] = b0.x; Bs[0][ac + 1][ar0] = b0.y;
    Bs[0][ac + 2][ar0] = b0.z; Bs[0][ac + 3][ar0] = b0.w;
    Bs[0][ac + 0][ar1] = b1.x; Bs[0][ac + 1][ar1] = b1.y;
    Bs[0][ac + 2][ar1] = b1.z; Bs[0][ac + 3][ar1] = b1.w;
    __syncthreads();

    int nk = K / GKK;
    for (int kt = 0; kt < nk; kt++) {
        int cur = kt & 1;
        int nxt = cur ^ 1;
        bool more = (kt + 1) < nk;
        float4 na0, na1, nb0, nb1;
        if (more) {
            int off = (kt + 1) * GKK;
            na0 = av0ok ? *(const float4*)(Ap0 + off) : make_float4(0.f, 0.f, 0.f, 0.f);
            na1 = av1ok ? *(const float4*)(Ap1 + off) : make_float4(0.f, 0.f, 0.f, 0.f);
            nb0 = *(const float4*)(Bp0 + off);
            nb1 = *(const float4*)(Bp1 + off);
        }
#pragma unroll
        for (int kk = 0; kk < GKK; kk++) {
            float4 avx = *(const float4*)&As[cur][kk][row];
            float4 avy = *(const float4*)&As[cur][kk][row + 4];
            float4 bvx = *(const float4*)&Bs[cur][kk][col];
            float4 bvy = *(const float4*)&Bs[cur][kk][col + 4];
            float a_[8] = {avx.x, avx.y, avx.z, avx.w, avy.x, avy.y, avy.z, avy.w};
            float b_[8] = {bvx.x, bvx.y, bvx.z, bvx.w, bvy.x, bvy.y, bvy.z, bvy.w};
#pragma unroll
            for (int i = 0; i < 8; i++)
#pragma unroll
                for (int j = 0; j < 8; j++)
                    acc[i][j] += a_[i] * b_[j];
        }
        if (more) {
            As[nxt][ac + 0][ar0] = na0.x; As[nxt][ac + 1][ar0] = na0.y;
            As[nxt][ac + 2][ar0] = na0.z; As[nxt][ac + 3][ar0] = na0.w;
            As[nxt][ac + 0][ar1] = na1.x; As[nxt][ac + 1][ar1] = na1.y;
            As[nxt][ac + 2][ar1] = na1.z; As[nxt][ac + 3][ar1] = na1.w;
            Bs[nxt][ac + 0][ar0] = nb0.x; Bs[nxt][ac + 1][ar0] = nb0.y;
            Bs[nxt][ac + 2][ar0] = nb0.z; Bs[nxt][ac + 3][ar0] = nb0.w;
            Bs[nxt][ac + 0][ar1] = nb1.x; Bs[nxt][ac + 1][ar1] = nb1.y;
            Bs[nxt][ac + 2][ar1] = nb1.z; Bs[nxt][ac + 3][ar1] = nb1.w;
            __syncthreads();
        }
    }

    // epilogue
    int cb0 = bn + col, cb1 = bn + col + 4;
    float4 bb0 = make_float4(0.f, 0.f, 0.f, 0.f);
    float4 bb1 = make_float4(0.f, 0.f, 0.f, 0.f);
    if (bias) {
        bb0 = *(const float4*)(bias + cb0);
        bb1 = *(const float4*)(bias + cb1);
    }
#pragma unroll
    for (int i = 0; i < 8; i++) {
        int r = bm + row + i;
        if (r >= M) continue;
        float4 rv0 = make_float4(0.f, 0.f, 0.f, 0.f);
        float4 rv1 = make_float4(0.f, 0.f, 0.f, 0.f);
        if (res) {
            rv0 = *(const float4*)(res + (size_t)r * Nn + cb0);
            rv1 = *(const float4*)(res + (size_t)r * Nn + cb1);
        }
        float4 o0, o1;
        o0.x = (acc[i][0] + bb0.x) * alpha + rv0.x;
        o0.y = (acc[i][1] + bb0.y) * alpha + rv0.y;
        o0.z = (acc[i][2] + bb0.z) * alpha + rv0.z;
        o0.w = (acc[i][3] + bb0.w) * alpha + rv0.w;
        o1.x = (acc[i][4] + bb1.x) * alpha + rv1.x;
        o1.y = (acc[i][5] + bb1.y) * alpha + rv1.y;
        o1.z = (acc[i][6] + bb1.z) * alpha + rv1.z;
        o1.w = (acc[i][7] + bb1.w) * alpha + rv1.w;
        if (act) {
            o0.x = o0.x > 0.f ? o0.x : 0.01f * o0.x;
            o0.y = o0.y > 0.f ? o0.y : 0.01f * o0.y;
            o0.z = o0.z > 0.f ? o0.z : 0.01f * o0.z;
            o0.w = o0.w > 0.f ? o0.w : 0.01f * o0.w;
            o1.x = o1.x > 0.f ? o1.x : 0.01f * o1.x;
            o1.y = o1.y > 0.f ? o1.y : 0.01f * o1.y;
            o1.z = o1.z > 0.f ? o1.z : 0.01f * o1.z;
            o1.w = o1.w > 0.f ? o1.w : 0.01f * o1.w;
        }
        *(float4*)(C + (size_t)r * Nn + cb0) = o0;
        *(float4*)(C + (size_t)r * Nn + cb1) = o1;
    }
}

// ---------------- fused edge pass: score + exp + den + unnormalized agg ----
// softmax max elided (|score| small, exp safe in fp32).
// Normalization deferred: sum(e*v)/den == sum((e/den)*v).
__global__ void edge_fused_kernel() {
    int gwarp = (blockIdx.x * blockDim.x + threadIdx.x) >> 5;
    if (gwarp >= ETOT) return;
    int lane = threadIdx.x & 31;
    int s = g_src[gwarp];
    int d = g_dst[gwarp];
    float4 q4 = *(const float4*)(g_q + (size_t)d * DDIM + lane * 4);
    float4 k4 = *(const float4*)(g_k + (size_t)s * DDIM + lane * 4);
    float p = q4.x * k4.x + q4.y * k4.y + q4.z * k4.z + q4.w * k4.w;
    p += __shfl_xor_sync(0xffffffffu, p, 1);
    p += __shfl_xor_sync(0xffffffffu, p, 2);
    float e = __expf(p);  // same across each 4-lane head group
    if ((lane & 3) == 0)
        atomicAdd(&g_den[d * NH + (lane >> 2)], e);
    float4 v4 = *(const float4*)(g_v + (size_t)s * DDIM + lane * 4);
    float* dst = g_agg + (size_t)d * DDIM + lane * 4;
    asm volatile("red.global.add.v4.f32 [%0], {%1, %2, %3, %4};"
                 :: "l"(dst), "f"(e * v4.x), "f"(e * v4.y),
                    "f"(e * v4.z), "f"(e * v4.w)
                 : "memory");
}

// ---------------- normalize aggregated messages ----------------------------
__global__ void normalize_kernel() {
    int i = blockIdx.x * blockDim.x + threadIdx.x;  // over float4 groups
    if (i >= NNODES * 32) return;
    int nodeh = i >> 2;  // node*8 + head (4 float4 per head)
    float inv = 1.f / (g_den[nodeh] + 1e-16f);
    float4* p = (float4*)g_agg + i;
    float4 v = *p;
    v.x *= inv; v.y *= inv; v.z *= inv; v.w *= inv;
    *p = v;
}

// ---------------- BatchNorm stats + apply ----------------------------------
__global__ void bn_stats_kernel(const float* __restrict__ X, int off) {
    int j = threadIdx.x;  // 128
    float s = 0.f, ss = 0.f;
    for (int r = blockIdx.x; r < NNODES; r += gridDim.x) {
        float x = X[(size_t)r * DDIM + j];
        s += x;
        ss += x * x;
    }
    atomicAdd(&g_stats[off + j], s);
    atomicAdd(&g_stats[off + DDIM + j], ss);
}

__global__ void bn_apply_kernel(const float* __restrict__ X, int off,
                                const float* __restrict__ gamma,
                                const float* __restrict__ beta,
                                float* __restrict__ Y) {
    int i = blockIdx.x * blockDim.x + threadIdx.x;
    if (i >= NNODES * DDIM) return;
    int j = i & (DDIM - 1);
    const float invn = 1.0f / NNODES;
    float mean = g_stats[off + j] * invn;
    float var = g_stats[off + DDIM + j] * invn - mean * mean;
    float x = X[i];
    Y[i] = (x - mean) * rsqrtf(var + EPS_BN) * gamma[j] + beta[j];
}

// ---------------- launch ----------------------------------------------------
extern "C" void kernel_launch(void* const* d_in, const int* in_sizes, int n_in,
                              void* d_out, int out_size) {
    const float* src    = (const float*)d_in[0];
    const unsigned int* ei = (const unsigned int*)d_in[1];
    const float* q_w    = (const float*)d_in[2];
    const float* q_b    = (const float*)d_in[3];
    const float* k_w    = (const float*)d_in[4];
    const float* v_w    = (const float*)d_in[5];
    const float* out_w  = (const float*)d_in[6];
    const float* out_b  = (const float*)d_in[7];
    const float* g1     = (const float*)d_in[8];
    const float* b1     = (const float*)d_in[9];
    const float* lin1_w = (const float*)d_in[10];
    const float* lin1_b = (const float*)d_in[11];
    const float* lin2_w = (const float*)d_in[12];
    const float* lin2_b = (const float*)d_in[13];
    const float* g2     = (const float*)d_in[14];
    const float* b2     = (const float*)d_in[15];
    float* out = (float*)d_out;

    float *pq, *pk, *pv, *pagg, *px1, *ptmp, *pff1;
    cudaGetSymbolAddress((void**)&pq,   g_q);
    cudaGetSymbolAddress((void**)&pk,   g_k);
    cudaGetSymbolAddress((void**)&pv,   g_v);
    cudaGetSymbolAddress((void**)&pagg, g_agg);
    cudaGetSymbolAddress((void**)&px1,  g_x1);
    cudaGetSymbolAddress((void**)&ptmp, g_tmp);
    cudaGetSymbolAddress((void**)&pff1, g_ff1);

    const int MB = (NNODES + GM - 1) / GM;  // 391
    const float scaling = 0.25f;            // HD^-0.5

    detect_kernel<<<1, 32>>>(ei);
    decode_kernel<<<(ETOT + 255) / 256, 256>>>(ei);
    zero_kernel<<<512, 256>>>();

    // q, k, v projections
    gemm_kernel<<<dim3(1, MB), 256>>>(src, q_w, q_b, nullptr, pq,
                                      NNODES, DDIM, DDIM, scaling, 0);
    gemm_kernel<<<dim3(1, MB), 256>>>(src, k_w, nullptr, nullptr, pk,
                                      NNODES, DDIM, DDIM, 1.0f, 0);
    gemm_kernel<<<dim3(1, MB), 256>>>(src, v_w, nullptr, nullptr, pv,
                                      NNODES, DDIM, DDIM, 1.0f, 0);

    // fused edge attention + deferred normalization
    int eblocks = (ETOT * 32 + 255) / 256;
    edge_fused_kernel<<<eblocks, 256>>>();
    normalize_kernel<<<(NNODES * 32 + 255) / 256, 256>>>();

    // out projection + residual
    gemm_kernel<<<dim3(1, MB), 256>>>(pagg, out_w, out_b, src, ptmp,
                                      NNODES, DDIM, DDIM, 1.0f, 0);

    // BN1
    bn_stats_kernel<<<512, 128>>>(ptmp, 0);
    bn_apply_kernel<<<(NNODES * DDIM + 255) / 256, 256>>>(ptmp, 0, g1, b1, px1);

    // FFN
    gemm_kernel<<<dim3(FDIM / GN, MB), 256>>>(px1, lin1_w, lin1_b, nullptr, pff1,
                                              NNODES, FDIM, DDIM, 1.0f, 1);
    gemm_kernel<<<dim3(1, MB), 256>>>(pff1, lin2_w, lin2_b, px1, ptmp,
                                      NNODES, DDIM, FDIM, 1.0f, 0);

    // BN2 -> output
    bn_stats_kernel<<<512, 128>>>(ptmp, 256);
    bn_apply_kernel<<<(NNODES * DDIM + 255) / 256, 256>>>(ptmp, 256, g2, b2, out);
}

// round 4
// speedup vs baseline: 1.5184x; 1.1759x over previous
#include <cuda_runtime.h>

#define NNODES 50000
#define DDIM 128
#define NH 8
#define HDIM 16
#define FDIM 512
#define E0 800000
#define ETOT 850000
#define EPS_BN 1e-5f
#define NCHUNK 49   // ceil(50000/1024)

// ---------------- scratch (device globals; no allocation allowed) ----------
__device__ __align__(16) float g_q[NNODES * DDIM];
__device__ __align__(16) float g_k[NNODES * DDIM];
__device__ __align__(16) float g_v[NNODES * DDIM];
__device__ __align__(16) float g_agg[NNODES * DDIM];
__device__ __align__(16) float g_x1[NNODES * DDIM];
__device__ __align__(16) float g_tmp[NNODES * DDIM];
__device__ __align__(16) float g_ff1[(size_t)NNODES * FDIM];
__device__ __align__(16) float g_stats[512];
__device__ int g_src[ETOT];
__device__ int g_dst[ETOT];
__device__ int g_csr[ETOT];
__device__ int g_deg[NNODES];
__device__ int g_rowptr[NNODES + 1];
__device__ int g_cursor[NNODES];
__device__ int g_csum[64];
__device__ int g_is64;

// ---------------- edge index dtype detection --------------------------------
__global__ void detect_kernel(const unsigned int* __restrict__ w) {
    if (threadIdx.x == 0 && blockIdx.x == 0) {
        int nz = 0;
        for (int i = 1; i < 256; i += 2) nz += (w[i] != 0u);
        g_is64 = (nz == 0) ? 1 : 0;
    }
}

// ---------------- zero (deg + stats) ----------------------------------------
__global__ void zero_kernel() {
    int i = blockIdx.x * blockDim.x + threadIdx.x;
    if (i < NNODES) g_deg[i] = 0;
    if (i < 512) g_stats[i] = 0.f;
}

// ---------------- decode edges + degree histogram ---------------------------
__global__ void decode_kernel(const unsigned int* __restrict__ w) {
    int e = blockIdx.x * blockDim.x + threadIdx.x;
    if (e >= ETOT) return;
    int s, d;
    if (e < E0) {
        if (g_is64) {
            s = (int)w[2 * (size_t)e];
            d = (int)w[2 * ((size_t)E0 + e)];
        } else {
            s = (int)w[e];
            d = (int)w[E0 + e];
        }
    } else {
        s = d = e - E0;
    }
    g_src[e] = s;
    g_dst[e] = d;
    atomicAdd(&g_deg[d], 1);
}

// ---------------- CSR build: 2-level exclusive scan + scatter ---------------
__global__ void scan1_kernel() {  // 49 blocks x 1024
    __shared__ int sh[1024];
    int t = threadIdx.x;
    int i = blockIdx.x * 1024 + t;
    int v = (i < NNODES) ? g_deg[i] : 0;
    sh[t] = v;
    __syncthreads();
    for (int off = 1; off < 1024; off <<= 1) {
        int x = (t >= off) ? sh[t - off] : 0;
        __syncthreads();
        sh[t] += x;
        __syncthreads();
    }
    if (i < NNODES) g_rowptr[i] = sh[t] - v;  // exclusive, chunk-local
    if (t == 1023) g_csum[blockIdx.x] = sh[1023];
}

__global__ void scan2_kernel() {  // 1 block
    if (threadIdx.x == 0) {
        int run = 0;
        for (int j = 0; j < NCHUNK; j++) {
            int x = g_csum[j];
            g_csum[j] = run;
            run += x;
        }
    }
}

__global__ void scan3_kernel() {
    int i = blockIdx.x * blockDim.x + threadIdx.x;
    if (i < NNODES) {
        int rp = g_rowptr[i] + g_csum[i >> 10];
        g_rowptr[i] = rp;
        g_cursor[i] = rp;
    }
    if (i == 0) g_rowptr[NNODES] = ETOT;
}

__global__ void scatter_kernel() {
    int e = blockIdx.x * blockDim.x + threadIdx.x;
    if (e >= ETOT) return;
    int pos = atomicAdd(&g_cursor[g_dst[e]], 1);
    g_csr[pos] = g_src[e];
}

// ---------------- tiled fp32 GEMM core --------------------------------------
// C = act((A@B^T + bias)*alpha + res). A[M,K], B[N,K] row-major.
// Block tile 128x128, k-tile 16, 8x8 microtile, warp tile 64x32 (conflict-free).
#define GM 128
#define GN 128
#define GKK 16

__device__ __forceinline__ void gemm_body(
    const float* __restrict__ A, const float* __restrict__ B,
    const float* __restrict__ bias, const float* __restrict__ res,
    float* __restrict__ C, int M, int Nn, int K, float alpha, int act,
    int bm, int bn)
{
    __shared__ __align__(16) float As[2][GKK][GM];
    __shared__ __align__(16) float Bs[2][GKK][GN];
    int tid = threadIdx.x;
    int warp = tid >> 5, lane = tid & 31;
    int wm = warp >> 2, wn = warp & 3;       // warps 2(M) x 4(N)
    int lr = lane >> 2, lc = lane & 3;       // lanes 8(M) x 4(N)
    int row = wm * 64 + lr * 8;              // 0..127
    int col = wn * 32 + lc * 8;              // 0..127

    // loaders: 2 float4 per thread per array per tile
    int ar0 = tid >> 2;              // 0..63
    int ar1 = ar0 + 64;              // 64..127
    int ac = (tid & 3) * 4;          // 0,4,8,12

    const float* Ap0 = A + (size_t)(bm + ar0) * K + ac;
    const float* Ap1 = A + (size_t)(bm + ar1) * K + ac;
    const float* Bp0 = B + (size_t)(bn + ar0) * K + ac;
    const float* Bp1 = B + (size_t)(bn + ar1) * K + ac;
    bool av0ok = (bm + ar0) < M;
    bool av1ok = (bm + ar1) < M;

    float acc[8][8] = {};

    float4 a0 = av0ok ? *(const float4*)Ap0 : make_float4(0.f, 0.f, 0.f, 0.f);
    float4 a1 = av1ok ? *(const float4*)Ap1 : make_float4(0.f, 0.f, 0.f, 0.f);
    float4 b0 = *(const float4*)Bp0;
    float4 b1 = *(const float4*)Bp1;
    As[0][ac + 0][ar0] = a0.x; As[0][ac + 1][ar0] = a0.y;
    As[0][ac + 2][ar0] = a0.z; As[0][ac + 3][ar0] = a0.w;
    As[0][ac + 0][ar1] = a1.x; As[0][ac + 1][ar1] = a1.y;
    As[0][ac + 2][ar1] = a1.z; As[0][ac + 3][ar1] = a1.w;
    Bs[0][ac + 0][ar0] = b0.x; Bs[0][ac + 1][ar0] = b0.y;
    Bs[0][ac + 2][ar0] = b0.z; Bs[0][ac + 3][ar0] = b0.w;
    Bs[0][ac + 0][ar1] = b1.x; Bs[0][ac + 1][ar1] = b1.y;
    Bs[0][ac + 2][ar1] = b1.z; Bs[0][ac + 3][ar1] = b1.w;
    __syncthreads();

    int nk = K / GKK;
    for (int kt = 0; kt < nk; kt++) {
        int cur = kt & 1;
        int nxt = cur ^ 1;
        bool more = (kt + 1) < nk;
        float4 na0, na1, nb0, nb1;
        if (more) {
            int off = (kt + 1) * GKK;
            na0 = av0ok ? *(const float4*)(Ap0 + off) : make_float4(0.f, 0.f, 0.f, 0.f);
            na1 = av1ok ? *(const float4*)(Ap1 + off) : make_float4(0.f, 0.f, 0.f, 0.f);
            nb0 = *(const float4*)(Bp0 + off);
            nb1 = *(const float4*)(Bp1 + off);
        }
#pragma unroll
        for (int kk = 0; kk < GKK; kk++) {
            float4 avx = *(const float4*)&As[cur][kk][row];
            float4 avy = *(const float4*)&As[cur][kk][row + 4];
            float4 bvx = *(const float4*)&Bs[cur][kk][col];
            float4 bvy = *(const float4*)&Bs[cur][kk][col + 4];
            float a_[8] = {avx.x, avx.y, avx.z, avx.w, avy.x, avy.y, avy.z, avy.w};
            float b_[8] = {bvx.x, bvx.y, bvx.z, bvx.w, bvy.x, bvy.y, bvy.z, bvy.w};
#pragma unroll
            for (int i = 0; i < 8; i++)
#pragma unroll
                for (int j = 0; j < 8; j++)
                    acc[i][j] += a_[i] * b_[j];
        }
        if (more) {
            As[nxt][ac + 0][ar0] = na0.x; As[nxt][ac + 1][ar0] = na0.y;
            As[nxt][ac + 2][ar0] = na0.z; As[nxt][ac + 3][ar0] = na0.w;
            As[nxt][ac + 0][ar1] = na1.x; As[nxt][ac + 1][ar1] = na1.y;
            As[nxt][ac + 2][ar1] = na1.z; As[nxt][ac + 3][ar1] = na1.w;
            Bs[nxt][ac + 0][ar0] = nb0.x; Bs[nxt][ac + 1][ar0] = nb0.y;
            Bs[nxt][ac + 2][ar0] = nb0.z; Bs[nxt][ac + 3][ar0] = nb0.w;
            Bs[nxt][ac + 0][ar1] = nb1.x; Bs[nxt][ac + 1][ar1] = nb1.y;
            Bs[nxt][ac + 2][ar1] = nb1.z; Bs[nxt][ac + 3][ar1] = nb1.w;
            __syncthreads();
        }
    }

    int cb0 = bn + col, cb1 = bn + col + 4;
    float4 bb0 = make_float4(0.f, 0.f, 0.f, 0.f);
    float4 bb1 = make_float4(0.f, 0.f, 0.f, 0.f);
    if (bias) {
        bb0 = *(const float4*)(bias + cb0);
        bb1 = *(const float4*)(bias + cb1);
    }
#pragma unroll
    for (int i = 0; i < 8; i++) {
        int r = bm + row + i;
        if (r >= M) continue;
        float4 rv0 = make_float4(0.f, 0.f, 0.f, 0.f);
        float4 rv1 = make_float4(0.f, 0.f, 0.f, 0.f);
        if (res) {
            rv0 = *(const float4*)(res + (size_t)r * Nn + cb0);
            rv1 = *(const float4*)(res + (size_t)r * Nn + cb1);
        }
        float4 o0, o1;
        o0.x = (acc[i][0] + bb0.x) * alpha + rv0.x;
        o0.y = (acc[i][1] + bb0.y) * alpha + rv0.y;
        o0.z = (acc[i][2] + bb0.z) * alpha + rv0.z;
        o0.w = (acc[i][3] + bb0.w) * alpha + rv0.w;
        o1.x = (acc[i][4] + bb1.x) * alpha + rv1.x;
        o1.y = (acc[i][5] + bb1.y) * alpha + rv1.y;
        o1.z = (acc[i][6] + bb1.z) * alpha + rv1.z;
        o1.w = (acc[i][7] + bb1.w) * alpha + rv1.w;
        if (act) {
            o0.x = o0.x > 0.f ? o0.x : 0.01f * o0.x;
            o0.y = o0.y > 0.f ? o0.y : 0.01f * o0.y;
            o0.z = o0.z > 0.f ? o0.z : 0.01f * o0.z;
            o0.w = o0.w > 0.f ? o0.w : 0.01f * o0.w;
            o1.x = o1.x > 0.f ? o1.x : 0.01f * o1.x;
            o1.y = o1.y > 0.f ? o1.y : 0.01f * o1.y;
            o1.z = o1.z > 0.f ? o1.z : 0.01f * o1.z;
            o1.w = o1.w > 0.f ? o1.w : 0.01f * o1.w;
        }
        *(float4*)(C + (size_t)r * Nn + cb0) = o0;
        *(float4*)(C + (size_t)r * Nn + cb1) = o1;
    }
}

__global__ __launch_bounds__(256, 2) void gemm_kernel(
    const float* __restrict__ A, const float* __restrict__ B,
    const float* __restrict__ bias, const float* __restrict__ res,
    float* __restrict__ C, int M, int Nn, int K, float alpha, int act)
{
    gemm_body(A, B, bias, res, C, M, Nn, K, alpha, act,
              blockIdx.y * GM, blockIdx.x * GN);
}

// merged q/k/v projection: blockIdx.z selects weight/output
__global__ __launch_bounds__(256, 2) void qkv_gemm_kernel(
    const float* __restrict__ A,
    const float* __restrict__ Wq, const float* __restrict__ Wk,
    const float* __restrict__ Wv, const float* __restrict__ qb)
{
    int z = blockIdx.z;
    const float* B = (z == 0) ? Wq : (z == 1) ? Wk : Wv;
    float* C = (z == 0) ? g_q : (z == 1) ? g_k : g_v;
    const float* bias = (z == 0) ? qb : nullptr;
    float alpha = (z == 0) ? 0.25f : 1.0f;
    gemm_body(A, B, bias, nullptr, C, NNODES, DDIM, DDIM, alpha, 0,
              blockIdx.y * GM, 0);
}

// ---------------- warp-per-node CSR attention aggregation -------------------
// softmax max elided (|score| small, exp safe in fp32); normalization deferred
__global__ void node_agg_kernel() {
    int node = (blockIdx.x * blockDim.x + threadIdx.x) >> 5;
    if (node >= NNODES) return;
    int lane = threadIdx.x & 31;
    float4 q4 = *(const float4*)(g_q + (size_t)node * DDIM + lane * 4);
    float4 acc = make_float4(0.f, 0.f, 0.f, 0.f);
    float den = 0.f;
    int beg = g_rowptr[node], end = g_rowptr[node + 1];
    for (int i = beg; i < end; i++) {
        int s = g_csr[i];
        float4 k4 = *(const float4*)(g_k + (size_t)s * DDIM + lane * 4);
        float p = q4.x * k4.x + q4.y * k4.y + q4.z * k4.z + q4.w * k4.w;
        p += __shfl_xor_sync(0xffffffffu, p, 1);
        p += __shfl_xor_sync(0xffffffffu, p, 2);
        float e = __expf(p);  // replicated across the 4 lanes of each head
        den += e;
        float4 v4 = *(const float4*)(g_v + (size_t)s * DDIM + lane * 4);
        acc.x += e * v4.x; acc.y += e * v4.y;
        acc.z += e * v4.z; acc.w += e * v4.w;
    }
    float inv = 1.f / (den + 1e-16f);
    acc.x *= inv; acc.y *= inv; acc.z *= inv; acc.w *= inv;
    *(float4*)(g_agg + (size_t)node * DDIM + lane * 4) = acc;
}

// ---------------- BatchNorm stats + apply ----------------------------------
__global__ void bn_stats_kernel(const float* __restrict__ X, int off) {
    int j = threadIdx.x;  // 128
    float s = 0.f, ss = 0.f;
    for (int r = blockIdx.x; r < NNODES; r += gridDim.x) {
        float x = X[(size_t)r * DDIM + j];
        s += x;
        ss += x * x;
    }
    atomicAdd(&g_stats[off + j], s);
    atomicAdd(&g_stats[off + DDIM + j], ss);
}

__global__ void bn_apply_kernel(const float* __restrict__ X, int off,
                                const float* __restrict__ gamma,
                                const float* __restrict__ beta,
                                float* __restrict__ Y) {
    int i = blockIdx.x * blockDim.x + threadIdx.x;
    if (i >= NNODES * DDIM) return;
    int j = i & (DDIM - 1);
    const float invn = 1.0f / NNODES;
    float mean = g_stats[off + j] * invn;
    float var = g_stats[off + DDIM + j] * invn - mean * mean;
    float x = X[i];
    Y[i] = (x - mean) * rsqrtf(var + EPS_BN) * gamma[j] + beta[j];
}

// ---------------- launch ----------------------------------------------------
extern "C" void kernel_launch(void* const* d_in, const int* in_sizes, int n_in,
                              void* d_out, int out_size) {
    const float* src    = (const float*)d_in[0];
    const unsigned int* ei = (const unsigned int*)d_in[1];
    const float* q_w    = (const float*)d_in[2];
    const float* q_b    = (const float*)d_in[3];
    const float* k_w    = (const float*)d_in[4];
    const float* v_w    = (const float*)d_in[5];
    const float* out_w  = (const float*)d_in[6];
    const float* out_b  = (const float*)d_in[7];
    const float* g1     = (const float*)d_in[8];
    const float* b1     = (const float*)d_in[9];
    const float* lin1_w = (const float*)d_in[10];
    const float* lin1_b = (const float*)d_in[11];
    const float* lin2_w = (const float*)d_in[12];
    const float* lin2_b = (const float*)d_in[13];
    const float* g2     = (const float*)d_in[14];
    const float* b2     = (const float*)d_in[15];
    float* out = (float*)d_out;

    float *pagg, *px1, *ptmp, *pff1;
    cudaGetSymbolAddress((void**)&pagg, g_agg);
    cudaGetSymbolAddress((void**)&px1,  g_x1);
    cudaGetSymbolAddress((void**)&ptmp, g_tmp);
    cudaGetSymbolAddress((void**)&pff1, g_ff1);

    const int MB = (NNODES + GM - 1) / GM;  // 391

    // edge decode + CSR build
    detect_kernel<<<1, 32>>>(ei);
    zero_kernel<<<(NNODES + 255) / 256, 256>>>();
    decode_kernel<<<(ETOT + 255) / 256, 256>>>(ei);
    scan1_kernel<<<NCHUNK, 1024>>>();
    scan2_kernel<<<1, 32>>>();
    scan3_kernel<<<(NNODES + 255) / 256, 256>>>();
    scatter_kernel<<<(ETOT + 255) / 256, 256>>>();

    // q, k, v projections (merged)
    qkv_gemm_kernel<<<dim3(1, MB, 3), 256>>>(src, q_w, k_w, v_w, q_b);

    // attention aggregation (CSR, warp per node)
    node_agg_kernel<<<(NNODES * 32 + 255) / 256, 256>>>();

    // out projection + residual
    gemm_kernel<<<dim3(1, MB), 256>>>(pagg, out_w, out_b, src, ptmp,
                                      NNODES, DDIM, DDIM, 1.0f, 0);

    // BN1
    bn_stats_kernel<<<512, 128>>>(ptmp, 0);
    bn_apply_kernel<<<(NNODES * DDIM + 255) / 256, 256>>>(ptmp, 0, g1, b1, px1);

    // FFN
    gemm_kernel<<<dim3(FDIM / GN, MB), 256>>>(px1, lin1_w, lin1_b, nullptr, pff1,
                                              NNODES, FDIM, DDIM, 1.0f, 1);
    gemm_kernel<<<dim3(1, MB), 256>>>(pff1, lin2_w, lin2_b, px1, ptmp,
                                      NNODES, DDIM, FDIM, 1.0f, 0);

    // BN2 -> output
    bn_stats_kernel<<<512, 128>>>(ptmp, 256);
    bn_apply_kernel<<<(NNODES * DDIM + 255) / 256, 256>>>(ptmp, 256, g2, b2, out);
}

// round 5
// speedup vs baseline: 2.0693x; 1.3628x over previous
#include <cuda_runtime.h>

#define NNODES 50000
#define DDIM 128
#define NH 8
#define HDIM 16
#define FDIM 512
#define E0 800000
#define ETOT 850000
#define EPS_BN 1e-5f
#define NCHUNK 49   // ceil(50000/1024)

// ---------------- scratch (device globals; no allocation allowed) ----------
__device__ __align__(16) float g_q[NNODES * DDIM];
__device__ __align__(16) float g_k[NNODES * DDIM];
__device__ __align__(16) float g_v[NNODES * DDIM];
__device__ __align__(16) float g_agg[NNODES * DDIM];
__device__ __align__(16) float g_x1[NNODES * DDIM];
__device__ __align__(16) float g_tmp[NNODES * DDIM];
__device__ __align__(16) float g_ff1[(size_t)NNODES * FDIM];
__device__ __align__(16) float g_stats[512];
__device__ int g_src[ETOT];
__device__ int g_dst[ETOT];
__device__ int g_csr[ETOT];
__device__ int g_deg[NNODES];
__device__ int g_rowptr[NNODES + 1];
__device__ int g_cursor[NNODES];
__device__ int g_csum[64];
__device__ int g_is64;

// ---------------- edge index dtype detection --------------------------------
__global__ void detect_kernel(const unsigned int* __restrict__ w) {
    if (threadIdx.x == 0 && blockIdx.x == 0) {
        int nz = 0;
        for (int i = 1; i < 256; i += 2) nz += (w[i] != 0u);
        g_is64 = (nz == 0) ? 1 : 0;
    }
}

__global__ void zero_kernel() {
    int i = blockIdx.x * blockDim.x + threadIdx.x;
    if (i < NNODES) g_deg[i] = 0;
    if (i < 512) g_stats[i] = 0.f;
}

__global__ void decode_kernel(const unsigned int* __restrict__ w) {
    int e = blockIdx.x * blockDim.x + threadIdx.x;
    if (e >= ETOT) return;
    int s, d;
    if (e < E0) {
        if (g_is64) {
            s = (int)w[2 * (size_t)e];
            d = (int)w[2 * ((size_t)E0 + e)];
        } else {
            s = (int)w[e];
            d = (int)w[E0 + e];
        }
    } else {
        s = d = e - E0;
    }
    g_src[e] = s;
    g_dst[e] = d;
    atomicAdd(&g_deg[d], 1);
}

// ---------------- CSR build --------------------------------------------------
__global__ void scan1_kernel() {
    __shared__ int sh[1024];
    int t = threadIdx.x;
    int i = blockIdx.x * 1024 + t;
    int v = (i < NNODES) ? g_deg[i] : 0;
    sh[t] = v;
    __syncthreads();
    for (int off = 1; off < 1024; off <<= 1) {
        int x = (t >= off) ? sh[t - off] : 0;
        __syncthreads();
        sh[t] += x;
        __syncthreads();
    }
    if (i < NNODES) g_rowptr[i] = sh[t] - v;
    if (t == 1023) g_csum[blockIdx.x] = sh[1023];
}

__global__ void scan2_kernel() {
    if (threadIdx.x == 0) {
        int run = 0;
        for (int j = 0; j < NCHUNK; j++) {
            int x = g_csum[j];
            g_csum[j] = run;
            run += x;
        }
    }
}

__global__ void scan3_kernel() {
    int i = blockIdx.x * blockDim.x + threadIdx.x;
    if (i < NNODES) {
        int rp = g_rowptr[i] + g_csum[i >> 10];
        g_rowptr[i] = rp;
        g_cursor[i] = rp;
    }
    if (i == 0) g_rowptr[NNODES] = ETOT;
}

__global__ void scatter_kernel() {
    int e = blockIdx.x * blockDim.x + threadIdx.x;
    if (e >= ETOT) return;
    int pos = atomicAdd(&g_cursor[g_dst[e]], 1);
    g_csr[pos] = g_src[e];
}

// ---------------- TF32 tensor-core GEMM -------------------------------------
// C = act((A@B^T + bias)*alpha + res). A[M,K], B[N,K] row-major.
// Block 128x128, k-tile 16, warp tile 64x32 (4x4 m16n8k8 mma tiles).
#define GM 128
#define GN 128
#define KT 16
#define SROW 136   // stride ≡ 8 (mod 32): conflict-free fragment reads

__device__ __forceinline__ unsigned f2tf(float x) {
    unsigned r;
    asm("cvt.rna.tf32.f32 %0, %1;" : "=r"(r) : "f"(x));
    return r;
}

__device__ __forceinline__ void mma8(float c[4],
                                     unsigned a0, unsigned a1, unsigned a2, unsigned a3,
                                     unsigned b0, unsigned b1) {
    asm volatile(
        "mma.sync.aligned.m16n8k8.row.col.f32.tf32.tf32.f32 "
        "{%0,%1,%2,%3}, {%4,%5,%6,%7}, {%8,%9}, {%0,%1,%2,%3};"
        : "+f"(c[0]), "+f"(c[1]), "+f"(c[2]), "+f"(c[3])
        : "r"(a0), "r"(a1), "r"(a2), "r"(a3), "r"(b0), "r"(b1));
}

__device__ __forceinline__ float2 lrelu2(float2 o, int act) {
    if (act) {
        o.x = o.x > 0.f ? o.x : 0.01f * o.x;
        o.y = o.y > 0.f ? o.y : 0.01f * o.y;
    }
    return o;
}

__device__ __forceinline__ void gemm_body(
    const float* __restrict__ A, const float* __restrict__ B,
    const float* __restrict__ bias, const float* __restrict__ res,
    float* __restrict__ C, int M, int Nn, int K, float alpha, int act,
    int bm, int bn)
{
    __shared__ unsigned As[2][KT][SROW];
    __shared__ unsigned Bs[2][KT][SROW];
    int tid = threadIdx.x;
    int warp = tid >> 5, lane = tid & 31;
    int wm = warp >> 2, wn = warp & 3;    // 2(M) x 4(N) warps
    int gid = lane >> 2, ctg = lane & 3;  // mma group / thread-in-group

    // loader: thread covers row (tid&127), k-cols [half*8, half*8+8)
    int lrow = tid & 127;
    int lhalf = tid >> 7;
    const float* Ap = A + (size_t)(bm + lrow) * K + lhalf * 8;
    const float* Bp = B + (size_t)(bn + lrow) * K + lhalf * 8;
    bool aok = (bm + lrow) < M;

    float c[4][4][4];
#pragma unroll
    for (int mt = 0; mt < 4; mt++)
#pragma unroll
        for (int nt = 0; nt < 4; nt++)
#pragma unroll
            for (int r = 0; r < 4; r++) c[mt][nt][r] = 0.f;

    const float4 z4 = make_float4(0.f, 0.f, 0.f, 0.f);
    float4 a0v = aok ? *(const float4*)Ap : z4;
    float4 a1v = aok ? *(const float4*)(Ap + 4) : z4;
    float4 b0v = *(const float4*)Bp;
    float4 b1v = *(const float4*)(Bp + 4);
    {
        int kb = lhalf * 8;
        As[0][kb + 0][lrow] = f2tf(a0v.x); As[0][kb + 1][lrow] = f2tf(a0v.y);
        As[0][kb + 2][lrow] = f2tf(a0v.z); As[0][kb + 3][lrow] = f2tf(a0v.w);
        As[0][kb + 4][lrow] = f2tf(a1v.x); As[0][kb + 5][lrow] = f2tf(a1v.y);
        As[0][kb + 6][lrow] = f2tf(a1v.z); As[0][kb + 7][lrow] = f2tf(a1v.w);
        Bs[0][kb + 0][lrow] = f2tf(b0v.x); Bs[0][kb + 1][lrow] = f2tf(b0v.y);
        Bs[0][kb + 2][lrow] = f2tf(b0v.z); Bs[0][kb + 3][lrow] = f2tf(b0v.w);
        Bs[0][kb + 4][lrow] = f2tf(b1v.x); Bs[0][kb + 5][lrow] = f2tf(b1v.y);
        Bs[0][kb + 6][lrow] = f2tf(b1v.z); Bs[0][kb + 7][lrow] = f2tf(b1v.w);
    }
    __syncthreads();

    int mbase = wm * 64 + gid;
    int nbase = wn * 32 + gid;
    int nk = K / KT;
    for (int kt = 0; kt < nk; kt++) {
        int cur = kt & 1;
        int nxt = cur ^ 1;
        bool more = (kt + 1) < nk;
        if (more) {
            int off = (kt + 1) * KT;
            a0v = aok ? *(const float4*)(Ap + off) : z4;
            a1v = aok ? *(const float4*)(Ap + off + 4) : z4;
            b0v = *(const float4*)(Bp + off);
            b1v = *(const float4*)(Bp + off + 4);
        }
#pragma unroll
        for (int ks = 0; ks < 2; ks++) {
            int kk = ks * 8;
            unsigned af[4][4], bf[4][2];
#pragma unroll
            for (int mt = 0; mt < 4; mt++) {
                int m = mbase + mt * 16;
                af[mt][0] = As[cur][kk + ctg][m];
                af[mt][1] = As[cur][kk + ctg][m + 8];
                af[mt][2] = As[cur][kk + ctg + 4][m];
                af[mt][3] = As[cur][kk + ctg + 4][m + 8];
            }
#pragma unroll
            for (int nt = 0; nt < 4; nt++) {
                int n = nbase + nt * 8;
                bf[nt][0] = Bs[cur][kk + ctg][n];
                bf[nt][1] = Bs[cur][kk + ctg + 4][n];
            }
#pragma unroll
            for (int mt = 0; mt < 4; mt++)
#pragma unroll
                for (int nt = 0; nt < 4; nt++)
                    mma8(c[mt][nt], af[mt][0], af[mt][1], af[mt][2], af[mt][3],
                         bf[nt][0], bf[nt][1]);
        }
        if (more) {
            int kb = lhalf * 8;
            As[nxt][kb + 0][lrow] = f2tf(a0v.x); As[nxt][kb + 1][lrow] = f2tf(a0v.y);
            As[nxt][kb + 2][lrow] = f2tf(a0v.z); As[nxt][kb + 3][lrow] = f2tf(a0v.w);
            As[nxt][kb + 4][lrow] = f2tf(a1v.x); As[nxt][kb + 5][lrow] = f2tf(a1v.y);
            As[nxt][kb + 6][lrow] = f2tf(a1v.z); As[nxt][kb + 7][lrow] = f2tf(a1v.w);
            Bs[nxt][kb + 0][lrow] = f2tf(b0v.x); Bs[nxt][kb + 1][lrow] = f2tf(b0v.y);
            Bs[nxt][kb + 2][lrow] = f2tf(b0v.z); Bs[nxt][kb + 3][lrow] = f2tf(b0v.w);
            Bs[nxt][kb + 4][lrow] = f2tf(b1v.x); Bs[nxt][kb + 5][lrow] = f2tf(b1v.y);
            Bs[nxt][kb + 6][lrow] = f2tf(b1v.z); Bs[nxt][kb + 7][lrow] = f2tf(b1v.w);
            __syncthreads();
        }
    }

    // epilogue: each thread owns rows {r0, r0+8}, cols {col, col+1} per tile
#pragma unroll
    for (int nt = 0; nt < 4; nt++) {
        int col = bn + wn * 32 + nt * 8 + 2 * ctg;
        float2 bb = make_float2(0.f, 0.f);
        if (bias) bb = *(const float2*)(bias + col);
#pragma unroll
        for (int mt = 0; mt < 4; mt++) {
            int r0 = bm + wm * 64 + mt * 16 + gid;
            int r1 = r0 + 8;
            if (r0 < M) {
                float2 rv = res ? *(const float2*)(res + (size_t)r0 * Nn + col)
                                : make_float2(0.f, 0.f);
                float2 o;
                o.x = (c[mt][nt][0] + bb.x) * alpha + rv.x;
                o.y = (c[mt][nt][1] + bb.y) * alpha + rv.y;
                *(float2*)(C + (size_t)r0 * Nn + col) = lrelu2(o, act);
            }
            if (r1 < M) {
                float2 rv = res ? *(const float2*)(res + (size_t)r1 * Nn + col)
                                : make_float2(0.f, 0.f);
                float2 o;
                o.x = (c[mt][nt][2] + bb.x) * alpha + rv.x;
                o.y = (c[mt][nt][3] + bb.y) * alpha + rv.y;
                *(float2*)(C + (size_t)r1 * Nn + col) = lrelu2(o, act);
            }
        }
    }
}

__global__ __launch_bounds__(256, 2) void gemm_kernel(
    const float* __restrict__ A, const float* __restrict__ B,
    const float* __restrict__ bias, const float* __restrict__ res,
    float* __restrict__ C, int M, int Nn, int K, float alpha, int act)
{
    gemm_body(A, B, bias, res, C, M, Nn, K, alpha, act,
              blockIdx.y * GM, blockIdx.x * GN);
}

__global__ __launch_bounds__(256, 2) void qkv_gemm_kernel(
    const float* __restrict__ A,
    const float* __restrict__ Wq, const float* __restrict__ Wk,
    const float* __restrict__ Wv, const float* __restrict__ qb)
{
    int z = blockIdx.z;
    const float* B = (z == 0) ? Wq : (z == 1) ? Wk : Wv;
    float* C = (z == 0) ? g_q : (z == 1) ? g_k : g_v;
    const float* bias = (z == 0) ? qb : nullptr;
    float alpha = (z == 0) ? 0.25f : 1.0f;
    gemm_body(A, B, bias, nullptr, C, NNODES, DDIM, DDIM, alpha, 0,
              blockIdx.y * GM, 0);
}

// ---------------- warp-per-node CSR attention aggregation -------------------
__global__ void node_agg_kernel() {
    int node = (blockIdx.x * blockDim.x + threadIdx.x) >> 5;
    if (node >= NNODES) return;
    int lane = threadIdx.x & 31;
    float4 q4 = *(const float4*)(g_q + (size_t)node * DDIM + lane * 4);
    float4 acc = make_float4(0.f, 0.f, 0.f, 0.f);
    float den = 0.f;
    int beg = g_rowptr[node], end = g_rowptr[node + 1];
    for (int i = beg; i < end; i++) {
        int s = g_csr[i];
        float4 k4 = *(const float4*)(g_k + (size_t)s * DDIM + lane * 4);
        float p = q4.x * k4.x + q4.y * k4.y + q4.z * k4.z + q4.w * k4.w;
        p += __shfl_xor_sync(0xffffffffu, p, 1);
        p += __shfl_xor_sync(0xffffffffu, p, 2);
        float e = __expf(p);
        den += e;
        float4 v4 = *(const float4*)(g_v + (size_t)s * DDIM + lane * 4);
        acc.x += e * v4.x; acc.y += e * v4.y;
        acc.z += e * v4.z; acc.w += e * v4.w;
    }
    float inv = 1.f / (den + 1e-16f);
    acc.x *= inv; acc.y *= inv; acc.z *= inv; acc.w *= inv;
    *(float4*)(g_agg + (size_t)node * DDIM + lane * 4) = acc;
}

// ---------------- BatchNorm stats + apply ----------------------------------
__global__ void bn_stats_kernel(const float* __restrict__ X, int off) {
    int j = threadIdx.x;
    float s = 0.f, ss = 0.f;
    for (int r = blockIdx.x; r < NNODES; r += gridDim.x) {
        float x = X[(size_t)r * DDIM + j];
        s += x;
        ss += x * x;
    }
    atomicAdd(&g_stats[off + j], s);
    atomicAdd(&g_stats[off + DDIM + j], ss);
}

__global__ void bn_apply_kernel(const float* __restrict__ X, int off,
                                const float* __restrict__ gamma,
                                const float* __restrict__ beta,
                                float* __restrict__ Y) {
    int i = blockIdx.x * blockDim.x + threadIdx.x;
    if (i >= NNODES * DDIM) return;
    int j = i & (DDIM - 1);
    const float invn = 1.0f / NNODES;
    float mean = g_stats[off + j] * invn;
    float var = g_stats[off + DDIM + j] * invn - mean * mean;
    float x = X[i];
    Y[i] = (x - mean) * rsqrtf(var + EPS_BN) * gamma[j] + beta[j];
}

// ---------------- launch ----------------------------------------------------
extern "C" void kernel_launch(void* const* d_in, const int* in_sizes, int n_in,
                              void* d_out, int out_size) {
    const float* src    = (const float*)d_in[0];
    const unsigned int* ei = (const unsigned int*)d_in[1];
    const float* q_w    = (const float*)d_in[2];
    const float* q_b    = (const float*)d_in[3];
    const float* k_w    = (const float*)d_in[4];
    const float* v_w    = (const float*)d_in[5];
    const float* out_w  = (const float*)d_in[6];
    const float* out_b  = (const float*)d_in[7];
    const float* g1     = (const float*)d_in[8];
    const float* b1     = (const float*)d_in[9];
    const float* lin1_w = (const float*)d_in[10];
    const float* lin1_b = (const float*)d_in[11];
    const float* lin2_w = (const float*)d_in[12];
    const float* lin2_b = (const float*)d_in[13];
    const float* g2     = (const float*)d_in[14];
    const float* b2     = (const float*)d_in[15];
    float* out = (float*)d_out;

    float *pagg, *px1, *ptmp, *pff1;
    cudaGetSymbolAddress((void**)&pagg, g_agg);
    cudaGetSymbolAddress((void**)&px1,  g_x1);
    cudaGetSymbolAddress((void**)&ptmp, g_tmp);
    cudaGetSymbolAddress((void**)&pff1, g_ff1);

    const int MB = (NNODES + GM - 1) / GM;  // 391

    // edge decode + CSR build
    detect_kernel<<<1, 32>>>(ei);
    zero_kernel<<<(NNODES + 255) / 256, 256>>>();
    decode_kernel<<<(ETOT + 255) / 256, 256>>>(ei);
    scan1_kernel<<<NCHUNK, 1024>>>();
    scan2_kernel<<<1, 32>>>();
    scan3_kernel<<<(NNODES + 255) / 256, 256>>>();
    scatter_kernel<<<(ETOT + 255) / 256, 256>>>();

    // q, k, v projections (merged, tf32 tensor cores)
    qkv_gemm_kernel<<<dim3(1, MB, 3), 256>>>(src, q_w, k_w, v_w, q_b);

    // attention aggregation (CSR, warp per node)
    node_agg_kernel<<<(NNODES * 32 + 255) / 256, 256>>>();

    // out projection + residual
    gemm_kernel<<<dim3(1, MB), 256>>>(pagg, out_w, out_b, src, ptmp,
                                      NNODES, DDIM, DDIM, 1.0f, 0);

    // BN1
    bn_stats_kernel<<<512, 128>>>(ptmp, 0);
    bn_apply_kernel<<<(NNODES * DDIM + 255) / 256, 256>>>(ptmp, 0, g1, b1, px1);

    // FFN
    gemm_kernel<<<dim3(FDIM / GN, MB), 256>>>(px1, lin1_w, lin1_b, nullptr, pff1,
                                              NNODES, FDIM, DDIM, 1.0f, 1);
    gemm_kernel<<<dim3(1, MB), 256>>>(pff1, lin2_w, lin2_b, px1, ptmp,
                                      NNODES, DDIM, FDIM, 1.0f, 0);

    // BN2 -> output
    bn_stats_kernel<<<512, 128>>>(ptmp, 256);
    bn_apply_kernel<<<(NNODES * DDIM + 255) / 256, 256>>>(ptmp, 256, g2, b2, out);
}